// round 15
// baseline (speedup 1.0000x reference)
#include <cuda_runtime.h>
#include <cuda_bf16.h>

#define BN 4
#define CH 3
#define HF 544
#define WF 960
#define H2 272
#define W2 480
#define RB 8
#define NB 34

__device__ float g_lg[BN*H2*W2];
__device__ float g_rg[BN*H2*W2];
__device__ double g_acc[10];
// 0 anchor_num 1 anchor_den 2 photo_err 3 photo_valid
// 4 sign_sum 5 mag_sum 6 cnt 7 smooth_dx 8 smooth_dy

__global__ void init_kernel(){ if (threadIdx.x < 10) g_acc[threadIdx.x] = 0.0; }

__device__ __forceinline__ float blockReduce(float v, float* buf){
  __syncthreads();
  #pragma unroll
  for (int o=16;o;o>>=1) v += __shfl_down_sync(0xffffffffu, v, o);
  int lane = threadIdx.x & 31, w = threadIdx.x >> 5;
  if (lane==0) buf[w]=v;
  __syncthreads();
  float r = 0.f;
  if (w==0){
    int nw = (blockDim.x + 31) >> 5;
    r = (lane < nw) ? buf[lane] : 0.f;
    #pragma unroll
    for (int o=16;o;o>>=1) r += __shfl_down_sync(0xffffffffu, r, o);
  }
  return r;
}

// ---- half-res grayscale ----------------------------------------------------
__global__ void down_kernel(const float* __restrict__ left, const float* __restrict__ right){
  int idx = blockIdx.x*blockDim.x + threadIdx.x;
  const int N = BN*H2*W2;
  if (idx >= N) return;
  int x = idx % W2; int t = idx / W2; int y = t % H2; int b = t / H2;
  size_t base = (((size_t)b*CH)*HF + (size_t)(2*y))*WF + (size_t)(2*x);
  float sl = 0.f, sr = 0.f;
  #pragma unroll
  for (int c=0;c<CH;c++){
    size_t o = base + (size_t)c*HF*WF;
    float2 a0 = *(const float2*)(left + o);
    float2 a1 = *(const float2*)(left + o + WF);
    sl += (a0.x + a0.y) + (a1.x + a1.y);
    float2 b0 = *(const float2*)(right + o);
    float2 b1 = *(const float2*)(right + o + WF);
    sr += (b0.x + b0.y) + (b1.x + b1.y);
  }
  g_lg[idx] = sl * (1.f/12.f);
  g_rg[idx] = sr * (1.f/12.f);
}

// ---- fused GT anchor + smoothness ------------------------------------------
__global__ void anchor_smooth_kernel(const float* __restrict__ pred, const float* __restrict__ gt,
                                     const float* __restrict__ conf, const float* __restrict__ occ,
                                     const float* __restrict__ left){
  __shared__ float buf[32];
  const int N = BN*HF*WF;
  const size_t cs = (size_t)HF*WF;
  float sn=0.f, sd=0.f, axs=0.f, ays=0.f;
  for (int i = blockIdx.x*blockDim.x + threadIdx.x; i < N; i += gridDim.x*blockDim.x){
    int x = i % WF; int t = i / WF; int y = t % HF; int b = t / HF;
    float g = gt[i];
    float pc = pred[i];
    if (g > 2.0f){
      float tt = conf[i]*occ[i];
      sd += tt;
      sn += tt*fabsf(pc-g);
    }
    size_t l0 = ((size_t)(b*CH)*HF + y)*WF + x;
    if (x < WF-1){
      float dd = fabsf(pred[i+1] - pc);
      float id = (fabsf(left[l0+1]-left[l0]) + fabsf(left[l0+cs+1]-left[l0+cs])
                + fabsf(left[l0+2*cs+1]-left[l0+2*cs])) * (1.f/3.f);
      axs += dd*__expf(-id);
    }
    if (y < HF-1){
      float dd = fabsf(pred[i+WF] - pc);
      float id = (fabsf(left[l0+WF]-left[l0]) + fabsf(left[l0+cs+WF]-left[l0+cs])
                + fabsf(left[l0+2*cs+WF]-left[l0+2*cs])) * (1.f/3.f);
      ays += dd*__expf(-id);
    }
  }
  float r = blockReduce(sn, buf);
  if (threadIdx.x==0) atomicAdd(&g_acc[0], (double)r);
  r = blockReduce(sd, buf);
  if (threadIdx.x==0) atomicAdd(&g_acc[1], (double)r);
  r = blockReduce(axs, buf);
  if (threadIdx.x==0) atomicAdd(&g_acc[7], (double)r);
  r = blockReduce(ays, buf);
  if (threadIdx.x==0) atomicAdd(&g_acc[8], (double)r);
}

// ---- NCC: band-sliding, 4-dg barrier batching -------------------------------
// smem layout (float offsets)
#define O_LG   0                 // [18][480]
#define O_RG   8640              // [18][528], col 24+c, zero pad
#define O_LMLS 18144             // float2 [8][480]
#define O_RMRS 25824             // float2 [8][528]
#define O_EDGE 34272             // float2 [8][480]  (10 edge-x * 48 d)
#define O_PVS  41952             // [16][508]  plane (q*4+k), data at +8
#define O_TMP  50080             // 4*544 temp
#define O_BUF  52256
#define NCC_SMEM_BYTES ((52256+32)*4)

__global__ void __launch_bounds__(512) ncc_kernel(const float* __restrict__ pred){
  extern __shared__ float sm[];
  float* LG   = sm + O_LG;
  float* RGm  = sm + O_RG;
  float2* LMLS = (float2*)(sm + O_LMLS);
  float2* RMRS = (float2*)(sm + O_RMRS);
  float2* EDGE = (float2*)(sm + O_EDGE);
  float* PVS  = sm + O_PVS;
  float* tL   = sm + O_TMP;
  float* tL2  = sm + O_TMP + 544;
  float* tR   = sm + O_TMP + 1088;
  float* tR2  = sm + O_TMP + 1632;
  float* BUF  = sm + O_BUF;

  const int tid = threadIdx.x;
  const int b  = blockIdx.x / NB;
  const int y0 = (blockIdx.x % NB) * RB;

  // load bands (rows y0-5 .. y0+12), zero outside image
  for (int i=tid;i<18*480;i+=512){
    int bi=i/480, xx=i-bi*480; int gy=y0-5+bi;
    LG[i] = ((unsigned)gy<(unsigned)H2)? g_lg[(b*H2+gy)*W2+xx] : 0.f;
  }
  for (int i=tid;i<18*528;i+=512){
    int bi=i/528, cc=i-bi*528; int gy=y0-5+bi; int c=cc-24;
    float v=0.f;
    if ((unsigned)gy<(unsigned)H2 && (unsigned)c<(unsigned)W2) v = g_rg[(b*H2+gy)*W2+c];
    RGm[i]=v;
  }
  for (int i=tid;i<16*508;i+=512) PVS[i]=0.f;
  for (int i=tid;i<4*544;i+=512) sm[O_TMP+i]=0.f;
  __syncthreads();

  // ---- per-row stats tables ----
  for (int yr=0;yr<RB;yr++){
    if (tid<480){
      float sL=0,sL2=0,sR=0,sR2=0;
      #pragma unroll
      for (int r=0;r<11;r++){
        float lv = LG[(yr+r)*480+tid];  sL+=lv; sL2=fmaf(lv,lv,sL2);
        float rv = RGm[(yr+r)*528+24+tid]; sR+=rv; sR2=fmaf(rv,rv,sR2);
      }
      tL[5+tid]=sL; tL2[5+tid]=sL2; tR[29+tid]=sR; tR2[29+tid]=sR2;
    }
    __syncthreads();
    if (tid<480){
      float s=0,s2=0;
      #pragma unroll
      for (int j=0;j<11;j++){ s+=tL[tid+j]; s2+=tL2[tid+j]; }
      float m=s*(1.f/121.f);
      LMLS[yr*480+tid] = make_float2(m, sqrtf(fmaxf(s2*(1.f/121.f)-m*m,1e-8f)));
    }
    for (int idx=tid; idx<528; idx+=512){
      float s=0,s2=0;
      #pragma unroll
      for (int j=0;j<11;j++){ s+=tR[idx+j]; s2+=tR2[idx+j]; }
      float m=s*(1.f/121.f);
      RMRS[yr*528+idx] = make_float2(m, sqrtf(fmaxf(s2*(1.f/121.f)-m*m,1e-8f)));
    }
    if (tid<480){
      int e=tid/48, di=tid-e*48;
      int xe = e<5 ? e : 470+e;
      int d  = di<24 ? di-24 : di-23;
      int c  = xe+d;
      int ra = max(max(c-5,d),0), rb2 = min(min(c+5,479+d),479);
      float s=0,s2=0;
      for (int cc=ra;cc<=rb2;cc++){ s+=tR[29+cc]; s2+=tR2[29+cc]; }
      float m=s*(1.f/121.f);
      EDGE[yr*480+tid] = make_float2(m, sqrtf(fmaxf(s2*(1.f/121.f)-m*m,1e-8f)));
    }
    __syncthreads();
  }

  // ---- main: thread (g,k): 4 cols x0..x0+3, 12 disparities di=dg*4+k ----
  const int g = tid>>2, k = tid&3;
  const int x0 = g<<2;
  const bool act = (tid < 480);

  float Pv[12][4];
  if (act){
    #pragma unroll
    for (int dg=0;dg<12;dg++){ Pv[dg][0]=0; Pv[dg][1]=0; Pv[dg][2]=0; Pv[dg][3]=0; }
    #pragma unroll 1
    for (int r=0;r<11;r++){
      float lv0=LG[r*480+x0], lv1=LG[r*480+x0+1], lv2=LG[r*480+x0+2], lv3=LG[r*480+x0+3];
      #pragma unroll
      for (int dg=0;dg<12;dg++){
        int di = dg*4+k; int d = di<24? di-24 : di-23;
        const float* rr = &RGm[r*528 + 24 + x0 + d];
        Pv[dg][0]=fmaf(lv0, rr[0], Pv[dg][0]);
        Pv[dg][1]=fmaf(lv1, rr[1], Pv[dg][1]);
        Pv[dg][2]=fmaf(lv2, rr[2], Pv[dg][2]);
        Pv[dg][3]=fmaf(lv3, rr[3], Pv[dg][3]);
      }
    }
  }

  float accS=0.f, accM=0.f, accC=0.f;

  #pragma unroll 1
  for (int yr=0;yr<RB;yr++){
    float2 lml[4];
    float bc[4], bi_[4];
    if (act){
      if (yr>0){
        const int rA=yr+10, rS=yr-1;
        float a0=LG[rA*480+x0], a1=LG[rA*480+x0+1], a2=LG[rA*480+x0+2], a3=LG[rA*480+x0+3];
        float s0=LG[rS*480+x0], s1=LG[rS*480+x0+1], s2=LG[rS*480+x0+2], s3=LG[rS*480+x0+3];
        #pragma unroll
        for (int dg=0;dg<12;dg++){
          int di = dg*4+k; int d = di<24? di-24 : di-23;
          const float* ra_ = &RGm[rA*528+24+x0+d];
          const float* rs_ = &RGm[rS*528+24+x0+d];
          Pv[dg][0]=fmaf(a0, ra_[0], fmaf(-s0, rs_[0], Pv[dg][0]));
          Pv[dg][1]=fmaf(a1, ra_[1], fmaf(-s1, rs_[1], Pv[dg][1]));
          Pv[dg][2]=fmaf(a2, ra_[2], fmaf(-s2, rs_[2], Pv[dg][2]));
          Pv[dg][3]=fmaf(a3, ra_[3], fmaf(-s3, rs_[3], Pv[dg][3]));
        }
      }
      #pragma unroll
      for (int c4=0;c4<4;c4++){ lml[c4]=LMLS[yr*480+x0+c4]; bc[c4]=-1.f; bi_[c4]=0.f; }
    }
    // 3 phases of 4 dg each: 2 barriers per phase
    #pragma unroll 1
    for (int dp=0;dp<3;dp++){
      if (act){
        #pragma unroll
        for (int q=0;q<4;q++){
          int dg = dp*4+q;
          float4 v = make_float4(Pv[dg][0],Pv[dg][1],Pv[dg][2],Pv[dg][3]);
          *(float4*)&PVS[(q*4+k)*508 + 8 + x0] = v;
        }
      }
      __syncthreads();
      if (act){
        #pragma unroll
        for (int q=0;q<4;q++){
          const int dg = dp*4+q;
          const int di = dg*4+k;
          const int d  = di<24? di-24 : di-23;
          const float* P = &PVS[(q*4+k)*508 + 8 + x0];
          float w0=P[-5],w1=P[-4],w2=P[-3],w3=P[-2],w4=P[-1],w5=P[0],w6=P[1],
                w7=P[2],w8=P[3],w9=P[4],w10=P[5],w11=P[6],w12=P[7],w13=P[8];
          float Cs = ((w0+w1)+(w2+w3)) + ((w4+w5)+(w6+w7)) + ((w8+w9)+w10);
          #pragma unroll
          for (int c4=0;c4<4;c4++){
            const int x = x0+c4;
            if (c4==1) Cs += w11 - w0;
            else if (c4==2) Cs += w12 - w1;
            else if (c4==3) Cs += w13 - w2;
            float2 rmv;
            if (x>=5 && x<=474) rmv = RMRS[yr*528+24+x+d];
            else { int e = (x<5)? x : x-470; rmv = EDGE[yr*480 + e*48 + di]; }
            float ncc = (Cs*(1.f/121.f) - lml[c4].x*rmv.x) / (lml[c4].y*rmv.y + 1e-8f);
            if (ncc > bc[c4]){ bc[c4]=ncc; bi_[c4]=(float)di; }
          }
        }
      }
      __syncthreads();
    }
    if (act){
      #pragma unroll
      for (int c4=0;c4<4;c4++){
        #pragma unroll
        for (int m=1;m<4;m<<=1){
          float oc = __shfl_xor_sync(0xffffffffu, bc[c4], m);
          float oi = __shfl_xor_sync(0xffffffffu, bi_[c4], m);
          if (oc > bc[c4] || (oc==bc[c4] && oi<bi_[c4])){ bc[c4]=oc; bi_[c4]=oi; }
        }
      }
      float mc = (k==0)?bc[0] :(k==1)?bc[1] :(k==2)?bc[2] :bc[3];
      float mi = (k==0)?bi_[0]:(k==1)?bi_[1]:(k==2)?bi_[2]:bi_[3];
      if (mc > 0.3f){
        int dii = (int)mi;
        int d = dii<24? dii-24 : dii-23;
        float nd = 2.f*(float)d;
        float sg = (d>0)? 1.f : -1.f;
        const float* pb = pred + ((size_t)b*HF + (size_t)(2*(y0+yr)))*WF + (size_t)(2*tid);
        float lss=0.f, lmm=0.f;
        #pragma unroll
        for (int dy=0;dy<2;dy++)
          #pragma unroll
          for (int dx=0;dx<2;dx++){
            float p = pb[dy*WF+dx];
            lss += fmaxf(-p*sg, 0.f);
            lmm += fabsf(p-nd);
          }
        accS += lss;
        accM += lmm*mc;
        accC += 4.f;
      }
    }
  }
  float r = blockReduce(accS, BUF);
  if (tid==0) atomicAdd(&g_acc[4], (double)r);
  r = blockReduce(accM, BUF);
  if (tid==0) atomicAdd(&g_acc[5], (double)r);
  r = blockReduce(accC, BUF);
  if (tid==0) atomicAdd(&g_acc[6], (double)r);
}

// ---- photometric (warp + SSIM + L1) ----------------------------------------
#define PTX 32
#define PTY 8
__global__ void __launch_bounds__(256) photo_kernel(const float* __restrict__ pred,
                                                    const float* __restrict__ left,
                                                    const float* __restrict__ right){
  __shared__ float lS[CH][PTY+2][PTX+2];
  __shared__ float wS[CH][PTY+2][PTX+2];
  __shared__ float xsS[PTY+2][PTX+2];
  __shared__ float buf[32];

  int b = blockIdx.z;
  int tx0 = blockIdx.x*PTX, ty0 = blockIdx.y*PTY;
  int tid = threadIdx.x;

  for (int i=tid; i<(PTY+2)*(PTX+2); i+=256){
    int ly = i/(PTX+2), lx = i - ly*(PTX+2);
    int gy = ty0 + ly - 1, gx = tx0 + lx - 1;
    float l0=0.f,l1=0.f,l2=0.f,w0=0.f,w1=0.f,w2=0.f,xs=-1.f;
    if ((unsigned)gy < (unsigned)HF && (unsigned)gx < (unsigned)WF){
      float dv = pred[((size_t)b*HF + gy)*WF + gx];
      xs = (float)gx - dv;
      float xc = fminf(fmaxf(xs, 0.f), (float)(WF-1));
      float x0f = floorf(xc);
      float wt = xc - x0f;
      int x0 = (int)x0f;
      int x1 = min(x0+1, WF-1);
      size_t rb0 = ((size_t)(b*CH)*HF + gy)*WF;
      const float* r0 = right + rb0;
      const float* r1 = r0 + (size_t)HF*WF;
      const float* r2 = r1 + (size_t)HF*WF;
      float omw = 1.f - wt;
      w0 = r0[x0]*omw + r0[x1]*wt;
      w1 = r1[x0]*omw + r1[x1]*wt;
      w2 = r2[x0]*omw + r2[x1]*wt;
      l0 = left[rb0 + gx];
      l1 = left[rb0 + (size_t)HF*WF + gx];
      l2 = left[rb0 + 2*(size_t)HF*WF + gx];
    }
    lS[0][ly][lx]=l0; lS[1][ly][lx]=l1; lS[2][ly][lx]=l2;
    wS[0][ly][lx]=w0; wS[1][ly][lx]=w1; wS[2][ly][lx]=w2;
    xsS[ly][lx]=xs;
  }
  __syncthreads();

  int lx = (tid % PTX) + 1, ly = (tid / PTX) + 1;
  const float C1 = 1e-4f, C2 = 9e-4f;
  float ss_sum = 0.f, l1_sum = 0.f;
  #pragma unroll
  for (int c=0;c<CH;c++){
    float sx=0.f, sy=0.f, sxx=0.f, syy=0.f, sxy=0.f;
    #pragma unroll
    for (int dy=-1;dy<=1;dy++)
      #pragma unroll
      for (int dx=-1;dx<=1;dx++){
        float xv = lS[c][ly+dy][lx+dx];
        float yv = wS[c][ly+dy][lx+dx];
        sx += xv; sy += yv;
        sxx = fmaf(xv,xv,sxx); syy = fmaf(yv,yv,syy); sxy = fmaf(xv,yv,sxy);
      }
    float mx = sx*(1.f/9.f), my = sy*(1.f/9.f);
    float vx = fmaxf(sxx*(1.f/9.f) - mx*mx, 0.f);
    float vy = fmaxf(syy*(1.f/9.f) - my*my, 0.f);
    float vxy = sxy*(1.f/9.f) - mx*my;
    float n = (2.f*mx*my + C1)*(2.f*vxy + C2);
    float den = (mx*mx + my*my + C1)*(vx + vy + C2);
    float dssim = (1.f - n/den)*0.5f;
    ss_sum += fminf(fmaxf(dssim, 0.f), 1.f);
    l1_sum += fabsf(lS[c][ly][lx] - wS[c][ly][lx]);
  }
  float xs = xsS[ly][lx];
  float valid = (xs > 0.f && xs < (float)(WF-1)) ? 1.f : 0.f;
  float err = (0.85f*ss_sum*(1.f/3.f) + 0.15f*l1_sum*(1.f/3.f)) * valid;

  float r = blockReduce(err, buf);
  if (tid==0) atomicAdd(&g_acc[2], (double)r);
  r = blockReduce(valid, buf);
  if (tid==0) atomicAdd(&g_acc[3], (double)r);
}

// ---- finalize --------------------------------------------------------------
__global__ void final_kernel(float* out){
  double anchor = g_acc[0] / fmax(g_acc[1], 1.0);
  double photo  = g_acc[2] / fmax(g_acc[3], 1.0);
  double n      = fmax(g_acc[6], 1.0);
  double smag   = 0.3*(g_acc[4]/n) + 0.7*(g_acc[5]/n);
  double sdx    = g_acc[7] / ((double)BN*HF*(WF-1));
  double sdy    = g_acc[8] / ((double)BN*(HF-1)*WF);
  out[0] = (float)(anchor + photo + 0.5*smag + 0.1*(sdx + sdy));
}

extern "C" void kernel_launch(void* const* d_in, const int* in_sizes, int n_in,
                              void* d_out, int out_size) {
  const float* pred  = (const float*)d_in[0];
  const float* gt    = (const float*)d_in[1];
  const float* conf  = (const float*)d_in[2];
  const float* occ   = (const float*)d_in[3];
  const float* left  = (const float*)d_in[4];
  const float* right = (const float*)d_in[5];
  float* out = (float*)d_out;

  cudaFuncSetAttribute(ncc_kernel, cudaFuncAttributeMaxDynamicSharedMemorySize, NCC_SMEM_BYTES);

  init_kernel<<<1, 32>>>();
  {
    int N = BN*H2*W2;
    down_kernel<<<(N+255)/256, 256>>>(left, right);
  }
  anchor_smooth_kernel<<<1024, 256>>>(pred, gt, conf, occ, left);
  ncc_kernel<<<BN*NB, 512, NCC_SMEM_BYTES>>>(pred);
  {
    dim3 g(WF/PTX, HF/PTY, BN);
    photo_kernel<<<g, 256>>>(pred, left, right);
  }
  final_kernel<<<1, 1>>>(out);
}

// round 16
// speedup vs baseline: 1.0769x; 1.0769x over previous
#include <cuda_runtime.h>
#include <cuda_bf16.h>

#define BN 4
#define CH 3
#define HF 544
#define WF 960
#define H2 272
#define W2 480
#define RB 8
#define NB 34
#define NT 960

__device__ float g_lg[BN*H2*W2];
__device__ float g_rg[BN*H2*W2];
__device__ double g_acc[10];
// 0 anchor_num 1 anchor_den 2 photo_err 3 photo_valid
// 4 sign_sum 5 mag_sum 6 cnt 7 smooth_dx 8 smooth_dy

__global__ void init_kernel(){ if (threadIdx.x < 10) g_acc[threadIdx.x] = 0.0; }

__device__ __forceinline__ float blockReduce(float v, float* buf){
  __syncthreads();
  #pragma unroll
  for (int o=16;o;o>>=1) v += __shfl_down_sync(0xffffffffu, v, o);
  int lane = threadIdx.x & 31, w = threadIdx.x >> 5;
  if (lane==0) buf[w]=v;
  __syncthreads();
  float r = 0.f;
  if (w==0){
    int nw = (blockDim.x + 31) >> 5;
    r = (lane < nw) ? buf[lane] : 0.f;
    #pragma unroll
    for (int o=16;o;o>>=1) r += __shfl_down_sync(0xffffffffu, r, o);
  }
  return r;
}

// ---- half-res grayscale ----------------------------------------------------
__global__ void down_kernel(const float* __restrict__ left, const float* __restrict__ right){
  int idx = blockIdx.x*blockDim.x + threadIdx.x;
  const int N = BN*H2*W2;
  if (idx >= N) return;
  int x = idx % W2; int t = idx / W2; int y = t % H2; int b = t / H2;
  size_t base = (((size_t)b*CH)*HF + (size_t)(2*y))*WF + (size_t)(2*x);
  float sl = 0.f, sr = 0.f;
  #pragma unroll
  for (int c=0;c<CH;c++){
    size_t o = base + (size_t)c*HF*WF;
    float2 a0 = *(const float2*)(left + o);
    float2 a1 = *(const float2*)(left + o + WF);
    sl += (a0.x + a0.y) + (a1.x + a1.y);
    float2 b0 = *(const float2*)(right + o);
    float2 b1 = *(const float2*)(right + o + WF);
    sr += (b0.x + b0.y) + (b1.x + b1.y);
  }
  g_lg[idx] = sl * (1.f/12.f);
  g_rg[idx] = sr * (1.f/12.f);
}

// ---- fused GT anchor + smoothness ------------------------------------------
__global__ void anchor_smooth_kernel(const float* __restrict__ pred, const float* __restrict__ gt,
                                     const float* __restrict__ conf, const float* __restrict__ occ,
                                     const float* __restrict__ left){
  __shared__ float buf[32];
  const int N = BN*HF*WF;
  const size_t cs = (size_t)HF*WF;
  float sn=0.f, sd=0.f, axs=0.f, ays=0.f;
  for (int i = blockIdx.x*blockDim.x + threadIdx.x; i < N; i += gridDim.x*blockDim.x){
    int x = i % WF; int t = i / WF; int y = t % HF; int b = t / HF;
    float g = gt[i];
    float pc = pred[i];
    if (g > 2.0f){
      float tt = conf[i]*occ[i];
      sd += tt;
      sn += tt*fabsf(pc-g);
    }
    size_t l0 = ((size_t)(b*CH)*HF + y)*WF + x;
    if (x < WF-1){
      float dd = fabsf(pred[i+1] - pc);
      float id = (fabsf(left[l0+1]-left[l0]) + fabsf(left[l0+cs+1]-left[l0+cs])
                + fabsf(left[l0+2*cs+1]-left[l0+2*cs])) * (1.f/3.f);
      axs += dd*__expf(-id);
    }
    if (y < HF-1){
      float dd = fabsf(pred[i+WF] - pc);
      float id = (fabsf(left[l0+WF]-left[l0]) + fabsf(left[l0+cs+WF]-left[l0+cs])
                + fabsf(left[l0+2*cs+WF]-left[l0+2*cs])) * (1.f/3.f);
      ays += dd*__expf(-id);
    }
  }
  float r = blockReduce(sn, buf);
  if (threadIdx.x==0) atomicAdd(&g_acc[0], (double)r);
  r = blockReduce(sd, buf);
  if (threadIdx.x==0) atomicAdd(&g_acc[1], (double)r);
  r = blockReduce(axs, buf);
  if (threadIdx.x==0) atomicAdd(&g_acc[7], (double)r);
  r = blockReduce(ays, buf);
  if (threadIdx.x==0) atomicAdd(&g_acc[8], (double)r);
}

// ---- NCC: band-sliding, 960 threads, 2 cols/thread, double-buffered PVS -----
// smem layout (float offsets)
#define O_LG   0                 // [18][480]
#define O_RG   8640              // [18][528], col 24+c, zero pad
#define O_LMLS 18144             // float2 [8][480]
#define O_RMRS 25824             // float2 [8][528]
#define O_EDGE 34272             // float2 [8][480]  (10 edge-x * 48 d)
#define O_PVS  41952             // [2 buf][4 k][508], data at +8
#define O_TMP  46016             // 4*544 temp
#define O_BUF  48192
#define NCC_SMEM_BYTES ((48192+32)*4)

__global__ void __launch_bounds__(NT,1) ncc_kernel(const float* __restrict__ pred){
  extern __shared__ float sm[];
  float* LG   = sm + O_LG;
  float* RGm  = sm + O_RG;
  float2* LMLS = (float2*)(sm + O_LMLS);
  float2* RMRS = (float2*)(sm + O_RMRS);
  float2* EDGE = (float2*)(sm + O_EDGE);
  float* PVS  = sm + O_PVS;
  float* tL   = sm + O_TMP;
  float* tL2  = sm + O_TMP + 544;
  float* tR   = sm + O_TMP + 1088;
  float* tR2  = sm + O_TMP + 1632;
  float* BUF  = sm + O_BUF;

  const int tid = threadIdx.x;
  const int b  = blockIdx.x / NB;
  const int y0 = (blockIdx.x % NB) * RB;

  // load bands (rows y0-5 .. y0+12), zero outside image
  for (int i=tid;i<18*480;i+=NT){
    int bi=i/480, xx=i-bi*480; int gy=y0-5+bi;
    LG[i] = ((unsigned)gy<(unsigned)H2)? g_lg[(b*H2+gy)*W2+xx] : 0.f;
  }
  for (int i=tid;i<18*528;i+=NT){
    int bi=i/528, cc=i-bi*528; int gy=y0-5+bi; int c=cc-24;
    float v=0.f;
    if ((unsigned)gy<(unsigned)H2 && (unsigned)c<(unsigned)W2) v = g_rg[(b*H2+gy)*W2+c];
    RGm[i]=v;
  }
  for (int i=tid;i<2*4*508;i+=NT) PVS[i]=0.f;
  for (int i=tid;i<4*544;i+=NT) sm[O_TMP+i]=0.f;
  __syncthreads();

  // ---- per-row stats tables ----
  for (int yr=0;yr<RB;yr++){
    if (tid<480){
      float sL=0,sL2=0,sR=0,sR2=0;
      #pragma unroll
      for (int r=0;r<11;r++){
        float lv = LG[(yr+r)*480+tid];  sL+=lv; sL2=fmaf(lv,lv,sL2);
        float rv = RGm[(yr+r)*528+24+tid]; sR+=rv; sR2=fmaf(rv,rv,sR2);
      }
      tL[5+tid]=sL; tL2[5+tid]=sL2; tR[29+tid]=sR; tR2[29+tid]=sR2;
    }
    __syncthreads();
    if (tid<480){
      float s=0,s2=0;
      #pragma unroll
      for (int j=0;j<11;j++){ s+=tL[tid+j]; s2+=tL2[tid+j]; }
      float m=s*(1.f/121.f);
      LMLS[yr*480+tid] = make_float2(m, sqrtf(fmaxf(s2*(1.f/121.f)-m*m,1e-8f)));
    }
    if (tid>=480 && tid<1008){
      int idx = tid-480;
      float s=0,s2=0;
      #pragma unroll
      for (int j=0;j<11;j++){ s+=tR[idx+j]; s2+=tR2[idx+j]; }
      float m=s*(1.f/121.f);
      RMRS[yr*528+idx] = make_float2(m, sqrtf(fmaxf(s2*(1.f/121.f)-m*m,1e-8f)));
    }
    // tid 480..959 covers idx 0..479 of RMRS? No: idx = tid-480 covers 0..479; need 0..527.
    if (tid<48){
      int idx = 480+tid;
      float s=0,s2=0;
      #pragma unroll
      for (int j=0;j<11;j++){ s+=tR[idx+j]; s2+=tR2[idx+j]; }
      float m=s*(1.f/121.f);
      RMRS[yr*528+idx] = make_float2(m, sqrtf(fmaxf(s2*(1.f/121.f)-m*m,1e-8f)));
    }
    __syncthreads();
    if (tid<480){
      int e=tid/48, di=tid-e*48;
      int xe = e<5 ? e : 470+e;
      int d  = di<24 ? di-24 : di-23;
      int c  = xe+d;
      int ra = max(max(c-5,d),0), rb2 = min(min(c+5,479+d),479);
      float s=0,s2=0;
      for (int cc=ra;cc<=rb2;cc++){ s+=tR[29+cc]; s2+=tR2[29+cc]; }
      float m=s*(1.f/121.f);
      EDGE[yr*480+tid] = make_float2(m, sqrtf(fmaxf(s2*(1.f/121.f)-m*m,1e-8f)));
    }
    __syncthreads();
  }

  // ---- main: thread (g,k): 2 cols x0,x0+1; 12 disparities di=dg*4+k -------
  const int g = tid>>2, k = tid&3;
  const int x0 = g<<1;   // 0..478

  float Pv[12][2];
  #pragma unroll
  for (int dg=0;dg<12;dg++){ Pv[dg][0]=0.f; Pv[dg][1]=0.f; }
  #pragma unroll 1
  for (int r=0;r<11;r++){
    float lv0=LG[r*480+x0], lv1=LG[r*480+x0+1];
    #pragma unroll
    for (int dg=0;dg<12;dg++){
      int di = dg*4+k; int d = di<24? di-24 : di-23;
      const float* rr = &RGm[r*528 + 24 + x0 + d];
      Pv[dg][0]=fmaf(lv0, rr[0], Pv[dg][0]);
      Pv[dg][1]=fmaf(lv1, rr[1], Pv[dg][1]);
    }
  }

  float accS=0.f, accM=0.f, accC=0.f;

  #pragma unroll 1
  for (int yr=0;yr<RB;yr++){
    if (yr>0){
      const int rA=yr+10, rS=yr-1;
      float a0=LG[rA*480+x0], a1=LG[rA*480+x0+1];
      float s0=LG[rS*480+x0], s1=LG[rS*480+x0+1];
      #pragma unroll
      for (int dg=0;dg<12;dg++){
        int di = dg*4+k; int d = di<24? di-24 : di-23;
        const float* ra_ = &RGm[rA*528+24+x0+d];
        const float* rs_ = &RGm[rS*528+24+x0+d];
        Pv[dg][0]=fmaf(a0, ra_[0], fmaf(-s0, rs_[0], Pv[dg][0]));
        Pv[dg][1]=fmaf(a1, ra_[1], fmaf(-s1, rs_[1], Pv[dg][1]));
      }
    }
    float2 lml0 = LMLS[yr*480+x0];
    float2 lml1 = LMLS[yr*480+x0+1];
    float bc0=-1.f, bc1=-1.f, bi0=0.f, bi1=0.f;

    #pragma unroll 1
    for (int dg=0;dg<12;dg++){
      float* Pw = &PVS[((dg&1)*4 + k)*508 + 8];
      *(float2*)&Pw[x0] = make_float2(Pv[dg][0], Pv[dg][1]);
      __syncthreads();
      const float* P = &Pw[x0];
      float w0=P[-5],w1=P[-4],w2=P[-3],w3=P[-2],w4=P[-1],w5=P[0],
            w6=P[1],w7=P[2],w8=P[3],w9=P[4],w10=P[5],w11=P[6];
      float Cs0 = ((w0+w1)+(w2+w3)) + ((w4+w5)+(w6+w7)) + ((w8+w9)+w10);
      float Cs1 = Cs0 + w11 - w0;
      const int di = dg*4+k;
      const int d  = di<24? di-24 : di-23;
      // col x0
      {
        const int x = x0;
        float2 rmv;
        if (x>=5 && x<=474) rmv = RMRS[yr*528+24+x+d];
        else { int e = (x<5)? x : x-470; rmv = EDGE[yr*480 + e*48 + di]; }
        float ncc = (Cs0*(1.f/121.f) - lml0.x*rmv.x) / (lml0.y*rmv.y + 1e-8f);
        if (ncc > bc0){ bc0=ncc; bi0=(float)di; }
      }
      // col x0+1
      {
        const int x = x0+1;
        float2 rmv;
        if (x>=5 && x<=474) rmv = RMRS[yr*528+24+x+d];
        else { int e = (x<5)? x : x-470; rmv = EDGE[yr*480 + e*48 + di]; }
        float ncc = (Cs1*(1.f/121.f) - lml1.x*rmv.x) / (lml1.y*rmv.y + 1e-8f);
        if (ncc > bc1){ bc1=ncc; bi1=(float)di; }
      }
    }
    __syncthreads();   // protect PVS buffers before next yr reuses them

    // combine over the 4 k-lanes (consecutive tids, same warp)
    #pragma unroll
    for (int m=1;m<4;m<<=1){
      float oc = __shfl_xor_sync(0xffffffffu, bc0, m);
      float oi = __shfl_xor_sync(0xffffffffu, bi0, m);
      if (oc > bc0 || (oc==bc0 && oi<bi0)){ bc0=oc; bi0=oi; }
      oc = __shfl_xor_sync(0xffffffffu, bc1, m);
      oi = __shfl_xor_sync(0xffffffffu, bi1, m);
      if (oc > bc1 || (oc==bc1 && oi<bi1)){ bc1=oc; bi1=oi; }
    }
    if (k < 2){
      float mc = (k==0)? bc0 : bc1;
      float mi = (k==0)? bi0 : bi1;
      if (mc > 0.3f){
        int dii = (int)mi;
        int d = dii<24? dii-24 : dii-23;
        float nd = 2.f*(float)d;
        float sg = (d>0)? 1.f : -1.f;
        const int x = x0 + k;
        const float* pb = pred + ((size_t)b*HF + (size_t)(2*(y0+yr)))*WF + (size_t)(2*x);
        float lss=0.f, lmm=0.f;
        #pragma unroll
        for (int dy=0;dy<2;dy++)
          #pragma unroll
          for (int dx=0;dx<2;dx++){
            float p = pb[dy*WF+dx];
            lss += fmaxf(-p*sg, 0.f);
            lmm += fabsf(p-nd);
          }
        accS += lss;
        accM += lmm*mc;
        accC += 4.f;
      }
    }
  }
  float r = blockReduce(accS, BUF);
  if (tid==0) atomicAdd(&g_acc[4], (double)r);
  r = blockReduce(accM, BUF);
  if (tid==0) atomicAdd(&g_acc[5], (double)r);
  r = blockReduce(accC, BUF);
  if (tid==0) atomicAdd(&g_acc[6], (double)r);
}

// ---- photometric (warp + SSIM + L1) ----------------------------------------
#define PTX 32
#define PTY 8
__global__ void __launch_bounds__(256) photo_kernel(const float* __restrict__ pred,
                                                    const float* __restrict__ left,
                                                    const float* __restrict__ right){
  __shared__ float lS[CH][PTY+2][PTX+2];
  __shared__ float wS[CH][PTY+2][PTX+2];
  __shared__ float xsS[PTY+2][PTX+2];
  __shared__ float buf[32];

  int b = blockIdx.z;
  int tx0 = blockIdx.x*PTX, ty0 = blockIdx.y*PTY;
  int tid = threadIdx.x;

  for (int i=tid; i<(PTY+2)*(PTX+2); i+=256){
    int ly = i/(PTX+2), lx = i - ly*(PTX+2);
    int gy = ty0 + ly - 1, gx = tx0 + lx - 1;
    float l0=0.f,l1=0.f,l2=0.f,w0=0.f,w1=0.f,w2=0.f,xs=-1.f;
    if ((unsigned)gy < (unsigned)HF && (unsigned)gx < (unsigned)WF){
      float dv = pred[((size_t)b*HF + gy)*WF + gx];
      xs = (float)gx - dv;
      float xc = fminf(fmaxf(xs, 0.f), (float)(WF-1));
      float x0f = floorf(xc);
      float wt = xc - x0f;
      int x0 = (int)x0f;
      int x1 = min(x0+1, WF-1);
      size_t rb0 = ((size_t)(b*CH)*HF + gy)*WF;
      const float* r0 = right + rb0;
      const float* r1 = r0 + (size_t)HF*WF;
      const float* r2 = r1 + (size_t)HF*WF;
      float omw = 1.f - wt;
      w0 = r0[x0]*omw + r0[x1]*wt;
      w1 = r1[x0]*omw + r1[x1]*wt;
      w2 = r2[x0]*omw + r2[x1]*wt;
      l0 = left[rb0 + gx];
      l1 = left[rb0 + (size_t)HF*WF + gx];
      l2 = left[rb0 + 2*(size_t)HF*WF + gx];
    }
    lS[0][ly][lx]=l0; lS[1][ly][lx]=l1; lS[2][ly][lx]=l2;
    wS[0][ly][lx]=w0; wS[1][ly][lx]=w1; wS[2][ly][lx]=w2;
    xsS[ly][lx]=xs;
  }
  __syncthreads();

  int lx = (tid % PTX) + 1, ly = (tid / PTX) + 1;
  const float C1 = 1e-4f, C2 = 9e-4f;
  float ss_sum = 0.f, l1_sum = 0.f;
  #pragma unroll
  for (int c=0;c<CH;c++){
    float sx=0.f, sy=0.f, sxx=0.f, syy=0.f, sxy=0.f;
    #pragma unroll
    for (int dy=-1;dy<=1;dy++)
      #pragma unroll
      for (int dx=-1;dx<=1;dx++){
        float xv = lS[c][ly+dy][lx+dx];
        float yv = wS[c][ly+dy][lx+dx];
        sx += xv; sy += yv;
        sxx = fmaf(xv,xv,sxx); syy = fmaf(yv,yv,syy); sxy = fmaf(xv,yv,sxy);
      }
    float mx = sx*(1.f/9.f), my = sy*(1.f/9.f);
    float vx = fmaxf(sxx*(1.f/9.f) - mx*mx, 0.f);
    float vy = fmaxf(syy*(1.f/9.f) - my*my, 0.f);
    float vxy = sxy*(1.f/9.f) - mx*my;
    float n = (2.f*mx*my + C1)*(2.f*vxy + C2);
    float den = (mx*mx + my*my + C1)*(vx + vy + C2);
    float dssim = (1.f - n/den)*0.5f;
    ss_sum += fminf(fmaxf(dssim, 0.f), 1.f);
    l1_sum += fabsf(lS[c][ly][lx] - wS[c][ly][lx]);
  }
  float xs = xsS[ly][lx];
  float valid = (xs > 0.f && xs < (float)(WF-1)) ? 1.f : 0.f;
  float err = (0.85f*ss_sum*(1.f/3.f) + 0.15f*l1_sum*(1.f/3.f)) * valid;

  float r = blockReduce(err, buf);
  if (tid==0) atomicAdd(&g_acc[2], (double)r);
  r = blockReduce(valid, buf);
  if (tid==0) atomicAdd(&g_acc[3], (double)r);
}

// ---- finalize --------------------------------------------------------------
__global__ void final_kernel(float* out){
  double anchor = g_acc[0] / fmax(g_acc[1], 1.0);
  double photo  = g_acc[2] / fmax(g_acc[3], 1.0);
  double n      = fmax(g_acc[6], 1.0);
  double smag   = 0.3*(g_acc[4]/n) + 0.7*(g_acc[5]/n);
  double sdx    = g_acc[7] / ((double)BN*HF*(WF-1));
  double sdy    = g_acc[8] / ((double)BN*(HF-1)*WF);
  out[0] = (float)(anchor + photo + 0.5*smag + 0.1*(sdx + sdy));
}

extern "C" void kernel_launch(void* const* d_in, const int* in_sizes, int n_in,
                              void* d_out, int out_size) {
  const float* pred  = (const float*)d_in[0];
  const float* gt    = (const float*)d_in[1];
  const float* conf  = (const float*)d_in[2];
  const float* occ   = (const float*)d_in[3];
  const float* left  = (const float*)d_in[4];
  const float* right = (const float*)d_in[5];
  float* out = (float*)d_out;

  cudaFuncSetAttribute(ncc_kernel, cudaFuncAttributeMaxDynamicSharedMemorySize, NCC_SMEM_BYTES);

  init_kernel<<<1, 32>>>();
  {
    int N = BN*H2*W2;
    down_kernel<<<(N+255)/256, 256>>>(left, right);
  }
  anchor_smooth_kernel<<<1024, 256>>>(pred, gt, conf, occ, left);
  ncc_kernel<<<BN*NB, NT, NCC_SMEM_BYTES>>>(pred);
  {
    dim3 g(WF/PTX, HF/PTY, BN);
    photo_kernel<<<g, 256>>>(pred, left, right);
  }
  final_kernel<<<1, 1>>>(out);
}